// round 16
// baseline (speedup 1.0000x reference)
#include <cuda_runtime.h>
#include <cooperative_groups.h>

namespace cg = cooperative_groups;

#define BATCH   64
#define NGT     1024
#define MPRED   2048
#define THRESH2 256.0f    // 16.0^2
#define GDIM    32        // 32x32 grid of 16px cells (512 / 16)
#define NCELL   (GDIM * GDIM)

// FINAL KERNEL (best-measured structure; 9.3-9.6us kernel, ~10.4us total).
//
// Cluster of 2 CTAs (1024 threads) per batch; grid = 128. Each CTA bins the
// batch's 1024 gts into a 32x32 cell CSR in its own smem, then scans 1024
// preds (rank r -> preds [r*1024, ...)) against the 3x3 cell neighborhood —
// exactly equivalent to the full argmin (a pred's match only matters if its
// min d2 < 256 = 16px^2, and any gt within 16px of a pred lies in the 3x3
// neighborhood of the pred's cell). Both ranks atomicMin (gt -> min pred
// index) into RANK 0's s_best (DSMEM atomic for rank 1); cluster.sync();
// rank 0 gathers from an smem-staged pred slab. Single launch, no global
// scratch, graph-capture-safe.
//
// Scatter uses the count-phase atomicAdd's return value as the within-cell
// rank: position = s_off[cell] + rank (plain STS, no second atomic pass).
// Within-cell order differs from insertion order, but the argmin key is
// order-invariant, so the result is bit-identical.
//
// Argmin: ONE u64 min over key = (d2_bits << 32) | gi — valid because
// d2 >= 0 so IEEE bits order as unsigned ints. Init key = bits(256.0f)<<32
// folds the threshold: strict <, and min-gi-within-min-d2 reproduces
// jnp.argmin's first-index tie rule order-invariantly.
//
// d2 uses __fadd_rn/__fmul_rn (no FMA contraction) -> bit-identical to the
// reference's mul-then-add; rel_err == 0.0 on all 15 measured benches.
__global__ __launch_bounds__(1024, 1) __cluster_dims__(2, 1, 1)
void lacss_match_kernel(
    const float2* __restrict__ gt,    // [BATCH, NGT]
    const float2* __restrict__ pred,  // [BATCH, MPRED]
    float2* __restrict__ out)         // [BATCH, NGT]
{
    __shared__ int    s_cnt[NCELL];      // per-cell counts
    __shared__ int    s_off[NCELL + 1];  // exclusive CSR offsets
    __shared__ float4 s_pt[NGT];         // {gx, gy, idx-as-float, pad} binned
    __shared__ int    s_best[NGT];       // min matched pred j per gt (rank0 authoritative)
    __shared__ float2 s_pred[MPRED];     // full pred slab (rank0 authoritative)
    __shared__ int    s_wsum[32];

    cg::cluster_group cluster = cg::this_cluster();
    const unsigned rank = cluster.block_rank();

    const int b    = blockIdx.x >> 1;
    const int tid  = threadIdx.x;
    const int lane = tid & 31;
    const int wid  = tid >> 5;

    // ---- prefetch both inputs (MLP=2, DRAM latency behind binning) ----
    const int j = (int)rank * 1024 + tid;          // this thread's pred
    const float2 p = pred[b * MPRED + j];
    const float2 g = gt[b * NGT + tid];

    s_cnt[tid]  = 0;
    s_best[tid] = MPRED;                 // sentinel: unmatched
    __syncthreads();

    // ---- stage pred slab into rank0's smem (overlapped with binning;
    //      visibility at the tail via cluster.sync) ----
    {
        float2* dst = (rank == 0) ? s_pred
                                  : cluster.map_shared_rank(s_pred, 0);
        dst[j] = p;                      // disjoint ranges per rank
    }

    // ---- count (cell = y/16 * 32 + x/16; *2^-4 exact); returned value is
    //      this gt's within-cell rank -> no second atomic pass needed ----
    const int gcell = (int)(g.y * 0.0625f) * GDIM + (int)(g.x * 0.0625f);
    const int r0 = atomicAdd(&s_cnt[gcell], 1);
    __syncthreads();

    // ---- exclusive prefix sum of s_cnt -> s_off ----
    int v   = s_cnt[tid];
    int inc = v;
    #pragma unroll
    for (int d = 1; d < 32; d <<= 1) {
        int n = __shfl_up_sync(0xFFFFFFFFu, inc, d);
        if (lane >= d) inc += n;
    }
    if (lane == 31) s_wsum[wid] = inc;
    __syncthreads();
    if (wid == 0) {
        int w  = s_wsum[lane];
        int wi = w;
        #pragma unroll
        for (int d = 1; d < 32; d <<= 1) {
            int n = __shfl_up_sync(0xFFFFFFFFu, wi, d);
            if (lane >= d) wi += n;
        }
        s_wsum[lane] = wi - w;           // exclusive offset of warp `lane`
    }
    __syncthreads();
    s_off[tid] = (inc - v) + s_wsum[wid];
    if (tid == 0) s_off[NCELL] = NGT;
    __syncthreads();

    // ---- scatter: position = CSR offset + count-phase rank (plain STS) ----
    s_pt[s_off[gcell] + r0] = make_float4(g.x, g.y, __int_as_float(tid), 0.f);
    __syncthreads();

    // ---- pred phase: one pred per thread, 3x3 neighborhood (3 runs),
    //      selection = single u64 min over (d2_bits, gi) ----
    {
        const int pcx = (int)(p.x * 0.0625f);
        const int pcy = (int)(p.y * 0.0625f);
        const int x0 = max(pcx - 1, 0), x1 = min(pcx + 1, GDIM - 1);
        const int y0 = max(pcy - 1, 0), y1 = min(pcy + 1, GDIM - 1);

        const unsigned long long K0 =
            ((unsigned long long)__float_as_uint(THRESH2)) << 32;
        unsigned long long best = K0;

        for (int cy = y0; cy <= y1; cy++) {
            const int ks = s_off[cy * GDIM + x0];
            const int ke = s_off[cy * GDIM + x1 + 1];   // cells contiguous in x
            for (int k = ks; k < ke; k++) {
                float4 q = s_pt[k];                     // one LDS.128
                float dx = __fadd_rn(p.x, -q.x);
                float dy = __fadd_rn(p.y, -q.y);
                float d2 = __fadd_rn(__fmul_rn(dx, dx), __fmul_rn(dy, dy));
                unsigned int bits = __float_as_uint(d2);
                unsigned int gi   = (unsigned int)__float_as_int(q.z);
                unsigned long long key;
                asm("mov.b64 %0, {%1, %2};" : "=l"(key) : "r"(gi), "r"(bits));
                best = (key < best) ? key : best;
            }
        }

        if (best < K0) {
            int bi = (int)(unsigned int)best;           // low word = gt index
            int* dst = (rank == 0) ? s_best
                                   : cluster.map_shared_rank(s_best, 0);
            atomicMin(&dst[bi], j);
        }
    }

    cluster.sync();                      // orders remote atomics + s_pred stores

    // ---- fused gather by rank 0: pure-SMEM reads ----
    if (rank == 0) {
        const int s = s_best[tid];
        out[b * NGT + tid] = (s < MPRED) ? s_pred[s] : g;
    }
}

extern "C" void kernel_launch(void* const* d_in, const int* in_sizes, int n_in,
                              void* d_out, int out_size) {
    const float2* gt   = (const float2*)d_in[0];   // gt_locations   [64,1024,2] f32
    const float2* pred = (const float2*)d_in[1];   // pred_locations [64,2048,2] f32
    float2* out = (float2*)d_out;                  // [64,1024,2] f32

    lacss_match_kernel<<<BATCH * 2, 1024>>>(gt, pred, out);
}